// round 5
// baseline (speedup 1.0000x reference)
#include <cuda_runtime.h>

// PureCartesianTensorProductO3Sparse — R5: f32x2 o-pair, dup-operand staging.
// 384 threads (12 warps), 1 CTA/SM, no reg cap below 170.
//
// Thread = (olane 0..7, slot 0..47); computes o1=olane, o2=olane+8 for 1 row.
// Weights in smem as (o1,o2)-interleaved pairs: [p][a][olane][2b+{0,1}], pad 36.
// Rows staged per side as: [0..32) dup L0, [32..128) dup L1, [128..272) plain L2.
// fma.rn.f32x2 computes both output channels per instruction; dup operands come
// straight from smem via 8-byte loads (no pack movs except rank-2 operands).

#define PACK2(d,x)    asm("mov.b64 %0, {%1, %1};" : "=l"(d) : "f"(x))
#define UNPK2(x,y,d)  asm("mov.b64 {%0, %1}, %2;" : "=f"(x), "=f"(y) : "l"(d))
#define FMA2(d,a,b,c) asm("fma.rn.f32x2 %0, %1, %2, %3;" : "=l"(d) : "l"(a), "l"(b), "l"(c))
#define ADD2(d,a,b)   asm("add.rn.f32x2 %0, %1, %2;" : "=l"(d) : "l"(a), "l"(b))

typedef unsigned long long u64;

constexpr int ROW_IN  = 416;
constexpr int THREADS = 384;               // 12 warps
constexpr int RPT     = 48;                // rows per tile (= THREADS/8)
constexpr int RSTR    = 276;               // staged row stride (floats)
constexpr int OL_STR  = 36;                // floats per (p,a,olane): 32 data + 4 pad
constexpr int A_STR   = 8 * OL_STR;        // 288
constexpr int PA_STR  = 16 * A_STR;        // per path: 4608
constexpr int WSMF    = 6 * PA_STR;        // 27648 floats = 108 KB
constexpr int WELEMS  = 6 * 16 * 16 * 16;  // 24576

__device__ __forceinline__ u64 ld64s(const float* p) {
    return *reinterpret_cast<const u64*>(p);
}

__global__ __launch_bounds__(THREADS, 1)
void tp_o3_kernel(const float* __restrict__ x1,
                  const float* __restrict__ x2,
                  const float* __restrict__ wgt,
                  float* __restrict__ out,
                  int N)
{
    extern __shared__ float smem[];
    float* ws  = smem;                     // 27648 floats
    float* x1s = smem + WSMF;              // 48 x 276
    float* x2s = x1s + RPT * RSTR;         // 48 x 276

    const int tid = threadIdx.x;

    // weights: gmem [p][o][a][b] -> smem pairs [p][a][olane][2b + (o>>3)]
    for (int idx = tid; idx < WELEMS; idx += THREADS) {
        int p = idx >> 12;
        int o = (idx >> 8) & 15;
        int a = (idx >> 4) & 15;
        int b = idx & 15;
        int olane = o & 7, oh = o >> 3;
        ws[(p * 16 + a) * A_STR + olane * OL_STR + 2 * b + oh] = wgt[idx];
    }
    __syncthreads();

    const int olane = tid & 7;
    const int slot  = tid >> 3;            // 0..47
    const int o1 = olane, o2 = olane + 8;
    const int ntiles = (N + RPT - 1) / RPT;

    const float* wp0 = ws + 0 * 16 * A_STR + olane * OL_STR;  // p stride = 16*A_STR
    // (path p base: ws + p*PA_STR + olane*OL_STR; computed inline below)

    for (int tile = blockIdx.x; tile < ntiles; tile += (int)gridDim.x) {
        const int row0  = tile * RPT;
        const int nrows = min(RPT, N - row0);

        // ---- stage rows: dup L0 (c<16 -> 2c,2c+1), dup L1 (16<=c<64 -> 32+2q),
        //                  plain L2 (c>=64 -> 128+(c-64))
        {
            const int tot = nrows * 208;
            for (int idx = tid; idx < tot; idx += THREADS) {
                int r = idx / 208, c = idx - r * 208;
                size_t g = (size_t)(row0 + r) * ROW_IN + c;
                float v1 = x1[g], v2 = x2[g];
                int base = r * RSTR;
                if (c < 64) {
                    int off = base + 2 * c + ((c < 16) ? 0 : 0);  // 2c for c<16; 32+2(c-16)=2c for c<64!
                    // note: 32 + 2*(c-16) == 2*c, so dup region is uniform: off = 2c
                    x1s[off] = v1; x1s[off + 1] = v1;
                    x2s[off] = v2; x2s[off + 1] = v2;
                } else {
                    int off = base + 64 + c;                      // 128 + (c-64) == 64 + c
                    x1s[off] = v1;
                    x2s[off] = v2;
                }
            }
        }
        __syncthreads();

        if (slot < nrows) {
            const float* xa = x1s + slot * RSTR;
            const float* xb = x2s + slot * RSTR;
            // dup offsets: value x[c] (c<64) at 2c; plain value x[c] (c>=64) at 64+c
            // A0[a]=x[a] -> dup 2a ; A1[a,i]=x[16+3a+i] -> dup 32+2(3a+i)
            // A2[a,k]=x[64+9a+k] -> plain 128+9a+k

            u64 acc0 = 0ull;
            u64 acc1[3] = {0ull,0ull,0ull};
            u64 acc2[9] = {0ull,0ull,0ull,0ull,0ull,0ull,0ull,0ull,0ull};

            // A0 dups cached (used by 3 stage1 passes)
            u64 A0d[16];
            #pragma unroll
            for (int a = 0; a < 16; a++) A0d[a] = ld64s(xa + 2 * a);

            u64 t[16];
            auto stage1 = [&](int p) {
                #pragma unroll
                for (int b = 0; b < 16; b++) t[b] = 0ull;
                const float* wb = ws + p * PA_STR + olane * OL_STR;
                #pragma unroll
                for (int a = 0; a < 16; a++) {
                    const ulonglong2* wv =
                        reinterpret_cast<const ulonglong2*>(wb + a * A_STR);
                    u64 av = A0d[a];
                    #pragma unroll
                    for (int j = 0; j < 8; j++) {
                        ulonglong2 q = wv[j];
                        FMA2(t[2*j],   av, q.x, t[2*j]);
                        FMA2(t[2*j+1], av, q.y, t[2*j+1]);
                    }
                }
            };

            // ---- path 0 (0,0): acc0 = sum_b t[b] * dup(B0[b])
            stage1(0);
            {
                u64 u0 = 0ull, u1 = 0ull;
                #pragma unroll
                for (int b = 0; b < 16; b += 2) {
                    FMA2(u0, t[b],   ld64s(xb + 2*b),     u0);
                    FMA2(u1, t[b+1], ld64s(xb + 2*b + 2), u1);
                }
                ADD2(acc0, u0, u1);
            }

            // ---- path 1 (0,1): acc1[i] += t[b] * dup(B1[b,i])
            stage1(1);
            #pragma unroll
            for (int b = 0; b < 16; b++) {
                u64 tb = t[b];
                FMA2(acc1[0], tb, ld64s(xb + 32 + 2*(3*b + 0)), acc1[0]);
                FMA2(acc1[1], tb, ld64s(xb + 32 + 2*(3*b + 1)), acc1[1]);
                FMA2(acc1[2], tb, ld64s(xb + 32 + 2*(3*b + 2)), acc1[2]);
            }

            // ---- path 2 (0,2): acc2[k] += t[b] * dup(B2[b,k])  (plain + pack)
            stage1(2);
            #pragma unroll
            for (int b = 0; b < 16; b++) {
                u64 tb = t[b];
                const float* e = xb + 128 + 9*b;
                #pragma unroll
                for (int k = 0; k < 9; k++) {
                    u64 ed; PACK2(ed, e[k]);
                    FMA2(acc2[k], tb, ed, acc2[k]);
                }
            }

            // ---- B0 dups cached for paths 3 & 5
            u64 B0d[16];
            #pragma unroll
            for (int b = 0; b < 16; b++) B0d[b] = ld64s(xb + 2 * b);

            auto dotB0 = [&](const float* wa) -> u64 {
                const ulonglong2* wv = reinterpret_cast<const ulonglong2*>(wa);
                u64 s0 = 0ull, s1 = 0ull;
                #pragma unroll
                for (int j = 0; j < 8; j++) {
                    ulonglong2 q = wv[j];
                    FMA2(s0, q.x, B0d[2*j],   s0);
                    FMA2(s1, q.y, B0d[2*j+1], s1);
                }
                u64 s; ADD2(s, s0, s1);
                return s;
            };

            // ---- path 3 (1,0): s = W3·B0 ; acc1[i] += s * dup(A1[a,i])
            {
                const float* wb = ws + 3 * PA_STR + olane * OL_STR;
                #pragma unroll
                for (int a = 0; a < 16; a++) {
                    u64 s = dotB0(wb + a * A_STR);
                    FMA2(acc1[0], s, ld64s(xa + 32 + 2*(3*a + 0)), acc1[0]);
                    FMA2(acc1[1], s, ld64s(xa + 32 + 2*(3*a + 1)), acc1[1]);
                    FMA2(acc1[2], s, ld64s(xa + 32 + 2*(3*a + 2)), acc1[2]);
                }
            }

            // ---- path 5 (2,0): s = W5·B0 ; acc2[k] += s * A2[a,k] (plain + pack)
            {
                const float* wb = ws + 5 * PA_STR + olane * OL_STR;
                #pragma unroll
                for (int a = 0; a < 16; a++) {
                    u64 s = dotB0(wb + a * A_STR);
                    const float* e = xa + 128 + 9*a;
                    #pragma unroll
                    for (int k = 0; k < 9; k++) {
                        u64 ed; PACK2(ed, e[k]);
                        FMA2(acc2[k], s, ed, acc2[k]);
                    }
                }
            }

            // ---- path 4 (1,1): v[j] = sum_b W4[·,a,b]·B1[b,j] ; acc2[3i+j] += A1[a,i]·v[j]
            {
                // E[j*16+b] = dup(B1[b,j]) cached in regs (48 u64)
                u64 E[48];
                #pragma unroll
                for (int j = 0; j < 3; j++)
                    #pragma unroll
                    for (int b = 0; b < 16; b++)
                        E[j*16 + b] = ld64s(xb + 32 + 2*(3*b + j));

                const float* wb = ws + 4 * PA_STR + olane * OL_STR;
                #pragma unroll
                for (int a = 0; a < 16; a++) {
                    const ulonglong2* wv =
                        reinterpret_cast<const ulonglong2*>(wb + a * A_STR);
                    u64 v0a=0ull,v0b=0ull,v1a=0ull,v1b=0ull,v2a=0ull,v2b=0ull;
                    #pragma unroll
                    for (int j = 0; j < 8; j++) {
                        ulonglong2 q = wv[j];
                        FMA2(v0a, q.x, E[0*16 + 2*j],   v0a);
                        FMA2(v0b, q.y, E[0*16 + 2*j+1], v0b);
                        FMA2(v1a, q.x, E[1*16 + 2*j],   v1a);
                        FMA2(v1b, q.y, E[1*16 + 2*j+1], v1b);
                        FMA2(v2a, q.x, E[2*16 + 2*j],   v2a);
                        FMA2(v2b, q.y, E[2*16 + 2*j+1], v2b);
                    }
                    u64 v0, v1, v2;
                    ADD2(v0, v0a, v0b); ADD2(v1, v1a, v1b); ADD2(v2, v2a, v2b);
                    u64 a0 = ld64s(xa + 32 + 2*(3*a + 0));
                    u64 a1 = ld64s(xa + 32 + 2*(3*a + 1));
                    u64 a2 = ld64s(xa + 32 + 2*(3*a + 2));
                    FMA2(acc2[0], a0, v0, acc2[0]);
                    FMA2(acc2[1], a0, v1, acc2[1]);
                    FMA2(acc2[2], a0, v2, acc2[2]);
                    FMA2(acc2[3], a1, v0, acc2[3]);
                    FMA2(acc2[4], a1, v1, acc2[4]);
                    FMA2(acc2[5], a1, v2, acc2[5]);
                    FMA2(acc2[6], a2, v0, acc2[6]);
                    FMA2(acc2[7], a2, v1, acc2[7]);
                    FMA2(acc2[8], a2, v2, acc2[8]);
                }
            }

            // ---- unpack + store first half of output row
            float* orow = out + (size_t)(row0 + slot) * ROW_IN;
            float p1, p2;
            UNPK2(p1, p2, acc0);
            orow[o1] = p1; orow[o2] = p2;
            #pragma unroll
            for (int i = 0; i < 3; i++) {
                UNPK2(p1, p2, acc1[i]);
                orow[16 + 3*o1 + i] = p1;
                orow[16 + 3*o2 + i] = p2;
            }
            #pragma unroll
            for (int k = 0; k < 9; k++) {
                UNPK2(p1, p2, acc2[k]);
                orow[64 + 9*o1 + k] = p1;
                orow[64 + 9*o2 + k] = p2;
            }
        }

        // ---- zero the s=1 half (cols 208..415)
        {
            float4 z = make_float4(0.f, 0.f, 0.f, 0.f);
            float4* og = reinterpret_cast<float4*>(out) + (size_t)row0 * 104;
            for (int i = tid; i < nrows * 52; i += THREADS) {
                int r = i / 52, c = i - r * 52;
                og[(size_t)r * 104 + 52 + c] = z;
            }
        }
        __syncthreads();
    }
    (void)wp0;
}

extern "C" void kernel_launch(void* const* d_in, const int* in_sizes, int n_in,
                              void* d_out, int out_size)
{
    const float* x1 = (const float*)d_in[0];
    const float* x2 = (const float*)d_in[1];
    const float* w  = (const float*)d_in[2];
    float* out = (float*)d_out;
    const int N = in_sizes[0] / ROW_IN;

    const int smem_bytes = (WSMF + 2 * RPT * RSTR) * (int)sizeof(float); // 216576

    int smcount = 0;
    cudaDeviceGetAttribute(&smcount, cudaDevAttrMultiProcessorCount, 0);
    if (smcount <= 0) smcount = 148;
    cudaFuncSetAttribute(tp_o3_kernel, cudaFuncAttributeMaxDynamicSharedMemorySize,
                         smem_bytes);

    tp_o3_kernel<<<smcount, THREADS, smem_bytes>>>(x1, x2, w, out, N);
}

// round 6
// speedup vs baseline: 1.4204x; 1.4204x over previous
#include <cuda_runtime.h>

// PureCartesianTensorProductO3Sparse — R6: R2 structure at 14 warps.
// Scalar fp32, 2 output channels per thread, path-4-first ordering and no
// A0 register cache to fit the 144-reg cap at 448 threads.

constexpr int NPATH    = 6;
constexpr int CC       = 16;
constexpr int WELEMS   = NPATH * CC * CC * CC;   // 24576
constexpr int BPAD     = 20;                     // padded b-stride
constexpr int WSM      = NPATH * CC * CC * BPAD; // 30720 floats
constexpr int ROW_IN   = 416;
constexpr int ROW_PAD  = 212;                    // staging stride (bank spread 20)
constexpr int RPT      = 56;                     // rows per tile
constexpr int THREADS  = 448;                    // 14 warps

__device__ __forceinline__ int ws_idx(int p, int a, int o) {
    return ((p * 256) + (a * 16) + o) * BPAD;
}

__global__ __launch_bounds__(THREADS, 1)
void tp_o3_kernel(const float* __restrict__ x1,
                  const float* __restrict__ x2,
                  const float* __restrict__ wgt,
                  float* __restrict__ out,
                  int N)
{
    extern __shared__ float smem[];
    float* ws  = smem;                    // 30720
    float* x1s = smem + WSM;              // 56 x 212
    float* x2s = x1s + RPT * ROW_PAD;     // 56 x 212

    const int tid = threadIdx.x;

    // Load + transpose weights: gmem [p][o][a][b] -> smem [p][a][o][b_pad]
    for (int idx = tid; idx < WELEMS; idx += THREADS) {
        int p = idx >> 12;
        int o = (idx >> 8) & 15;
        int a = (idx >> 4) & 15;
        int b = idx & 15;
        ws[ws_idx(p, a, o) + b] = wgt[idx];
    }
    __syncthreads();

    const int olane = tid & 7;
    const int slot  = tid >> 3;          // 0..55
    const int o1 = olane, o2 = olane + 8;
    const int ntiles = (N + RPT - 1) / RPT;

    for (int tile = blockIdx.x; tile < ntiles; tile += (int)gridDim.x) {
        const int row0  = tile * RPT;
        const int nrows = min(RPT, N - row0);

        // ---- stage used halves of rows into smem (float4, padded stride) ----
        {
            const float4* g1 = reinterpret_cast<const float4*>(x1) + (size_t)row0 * 104;
            const float4* g2 = reinterpret_cast<const float4*>(x2) + (size_t)row0 * 104;
            float4* s1 = reinterpret_cast<float4*>(x1s);
            float4* s2 = reinterpret_cast<float4*>(x2s);
            for (int i = tid; i < nrows * 52; i += THREADS) {
                int r = i / 52, c = i - r * 52;
                s1[r * 53 + c] = g1[(size_t)r * 104 + c];
                s2[r * 53 + c] = g2[(size_t)r * 104 + c];
            }
        }
        __syncthreads();

        if (slot < nrows) {
            const float* xa = x1s + slot * ROW_PAD;
            const float* xb = x2s + slot * ROW_PAD;

            float acc0_1 = 0.f, acc0_2 = 0.f;
            float acc1_1[3] = {0.f,0.f,0.f}, acc1_2[3] = {0.f,0.f,0.f};
            float acc2_1[9] = {0.f,0.f,0.f,0.f,0.f,0.f,0.f,0.f,0.f};
            float acc2_2[9] = {0.f,0.f,0.f,0.f,0.f,0.f,0.f,0.f,0.f};

            // ================= path 4 (1,1) FIRST (B1t peak isolated) ======
            {
                float B1t[3][16];
                #pragma unroll
                for (int b = 0; b < 16; b++) {
                    B1t[0][b] = xb[16 + 3*b + 0];
                    B1t[1][b] = xb[16 + 3*b + 1];
                    B1t[2][b] = xb[16 + 3*b + 2];
                }
                const float* w1 = ws + ws_idx(4, 0, o1);
                const float* w2 = ws + ws_idx(4, 0, o2);
                #pragma unroll
                for (int a = 0; a < 16; a++) {
                    float v1j[3], v2j[3];
                    #pragma unroll
                    for (int oo = 0; oo < 2; oo++) {
                        const float* wp = (oo == 0 ? w1 : w2) + a * (16 * BPAD);
                        const float4* wv = reinterpret_cast<const float4*>(wp);
                        float w[16];
                        float4 q0 = wv[0], q1 = wv[1], q2 = wv[2], q3 = wv[3];
                        w[0]=q0.x; w[1]=q0.y; w[2]=q0.z; w[3]=q0.w;
                        w[4]=q1.x; w[5]=q1.y; w[6]=q1.z; w[7]=q1.w;
                        w[8]=q2.x; w[9]=q2.y; w[10]=q2.z; w[11]=q2.w;
                        w[12]=q3.x; w[13]=q3.y; w[14]=q3.z; w[15]=q3.w;
                        float v0a=0.f,v0b=0.f,v1a=0.f,v1b=0.f,v2a=0.f,v2b=0.f;
                        #pragma unroll
                        for (int b = 0; b < 16; b += 2) {
                            v0a = fmaf(w[b],   B1t[0][b],   v0a);
                            v0b = fmaf(w[b+1], B1t[0][b+1], v0b);
                            v1a = fmaf(w[b],   B1t[1][b],   v1a);
                            v1b = fmaf(w[b+1], B1t[1][b+1], v1b);
                            v2a = fmaf(w[b],   B1t[2][b],   v2a);
                            v2b = fmaf(w[b+1], B1t[2][b+1], v2b);
                        }
                        float* vj = (oo == 0) ? v1j : v2j;
                        vj[0] = v0a + v0b; vj[1] = v1a + v1b; vj[2] = v2a + v2b;
                    }
                    float a10 = xa[16 + 3*a + 0];
                    float a11 = xa[16 + 3*a + 1];
                    float a12 = xa[16 + 3*a + 2];
                    acc2_1[0]=fmaf(a10,v1j[0],acc2_1[0]); acc2_1[1]=fmaf(a10,v1j[1],acc2_1[1]); acc2_1[2]=fmaf(a10,v1j[2],acc2_1[2]);
                    acc2_1[3]=fmaf(a11,v1j[0],acc2_1[3]); acc2_1[4]=fmaf(a11,v1j[1],acc2_1[4]); acc2_1[5]=fmaf(a11,v1j[2],acc2_1[5]);
                    acc2_1[6]=fmaf(a12,v1j[0],acc2_1[6]); acc2_1[7]=fmaf(a12,v1j[1],acc2_1[7]); acc2_1[8]=fmaf(a12,v1j[2],acc2_1[8]);
                    acc2_2[0]=fmaf(a10,v2j[0],acc2_2[0]); acc2_2[1]=fmaf(a10,v2j[1],acc2_2[1]); acc2_2[2]=fmaf(a10,v2j[2],acc2_2[2]);
                    acc2_2[3]=fmaf(a11,v2j[0],acc2_2[3]); acc2_2[4]=fmaf(a11,v2j[1],acc2_2[4]); acc2_2[5]=fmaf(a11,v2j[2],acc2_2[5]);
                    acc2_2[6]=fmaf(a12,v2j[0],acc2_2[6]); acc2_2[7]=fmaf(a12,v2j[1],acc2_2[7]); acc2_2[8]=fmaf(a12,v2j[2],acc2_2[8]);
                }
            }

            // ================= stage-1 paths 0, 1, 2 =======================
            // t1/t2[b] = sum_a xa[a] * W[p][a][o{1,2}][b]  (xa read via LDS bcast)
            auto stage1 = [&](int p, float (&t1)[16], float (&t2)[16]) {
                #pragma unroll
                for (int b = 0; b < 16; b++) { t1[b] = 0.f; t2[b] = 0.f; }
                const float* w1 = ws + ws_idx(p, 0, o1);
                const float* w2 = ws + ws_idx(p, 0, o2);
                #pragma unroll
                for (int a = 0; a < 16; a++) {
                    float av = xa[a];
                    const float4* v1 = reinterpret_cast<const float4*>(w1 + a * (16 * BPAD));
                    const float4* v2 = reinterpret_cast<const float4*>(w2 + a * (16 * BPAD));
                    float4 q;
                    q = v1[0]; t1[0] =fmaf(av,q.x,t1[0]);  t1[1] =fmaf(av,q.y,t1[1]);
                               t1[2] =fmaf(av,q.z,t1[2]);  t1[3] =fmaf(av,q.w,t1[3]);
                    q = v1[1]; t1[4] =fmaf(av,q.x,t1[4]);  t1[5] =fmaf(av,q.y,t1[5]);
                               t1[6] =fmaf(av,q.z,t1[6]);  t1[7] =fmaf(av,q.w,t1[7]);
                    q = v1[2]; t1[8] =fmaf(av,q.x,t1[8]);  t1[9] =fmaf(av,q.y,t1[9]);
                               t1[10]=fmaf(av,q.z,t1[10]); t1[11]=fmaf(av,q.w,t1[11]);
                    q = v1[3]; t1[12]=fmaf(av,q.x,t1[12]); t1[13]=fmaf(av,q.y,t1[13]);
                               t1[14]=fmaf(av,q.z,t1[14]); t1[15]=fmaf(av,q.w,t1[15]);
                    q = v2[0]; t2[0] =fmaf(av,q.x,t2[0]);  t2[1] =fmaf(av,q.y,t2[1]);
                               t2[2] =fmaf(av,q.z,t2[2]);  t2[3] =fmaf(av,q.w,t2[3]);
                    q = v2[1]; t2[4] =fmaf(av,q.x,t2[4]);  t2[5] =fmaf(av,q.y,t2[5]);
                               t2[6] =fmaf(av,q.z,t2[6]);  t2[7] =fmaf(av,q.w,t2[7]);
                    q = v2[2]; t2[8] =fmaf(av,q.x,t2[8]);  t2[9] =fmaf(av,q.y,t2[9]);
                               t2[10]=fmaf(av,q.z,t2[10]); t2[11]=fmaf(av,q.w,t2[11]);
                    q = v2[3]; t2[12]=fmaf(av,q.x,t2[12]); t2[13]=fmaf(av,q.y,t2[13]);
                               t2[14]=fmaf(av,q.z,t2[14]); t2[15]=fmaf(av,q.w,t2[15]);
                }
            };

            // ---- path 0 (0,0)
            {
                float t1[16], t2[16];
                stage1(0, t1, t2);
                float u1a=0.f,u1b=0.f,u2a=0.f,u2b=0.f;
                #pragma unroll
                for (int b = 0; b < 16; b += 2) {
                    float xb0 = xb[b], xb1 = xb[b+1];
                    u1a = fmaf(t1[b],   xb0, u1a);
                    u1b = fmaf(t1[b+1], xb1, u1b);
                    u2a = fmaf(t2[b],   xb0, u2a);
                    u2b = fmaf(t2[b+1], xb1, u2b);
                }
                acc0_1 = u1a + u1b;
                acc0_2 = u2a + u2b;
            }

            // ---- path 1 (0,1)
            {
                float t1[16], t2[16];
                stage1(1, t1, t2);
                #pragma unroll
                for (int b = 0; b < 16; b++) {
                    float e0 = xb[16 + 3*b + 0];
                    float e1 = xb[16 + 3*b + 1];
                    float e2 = xb[16 + 3*b + 2];
                    acc1_1[0] = fmaf(t1[b], e0, acc1_1[0]);
                    acc1_1[1] = fmaf(t1[b], e1, acc1_1[1]);
                    acc1_1[2] = fmaf(t1[b], e2, acc1_1[2]);
                    acc1_2[0] = fmaf(t2[b], e0, acc1_2[0]);
                    acc1_2[1] = fmaf(t2[b], e1, acc1_2[1]);
                    acc1_2[2] = fmaf(t2[b], e2, acc1_2[2]);
                }
            }

            // ---- path 2 (0,2)
            {
                float t1[16], t2[16];
                stage1(2, t1, t2);
                #pragma unroll
                for (int b = 0; b < 16; b++) {
                    float tb1 = t1[b], tb2 = t2[b];
                    #pragma unroll
                    for (int k = 0; k < 9; k++) {
                        float e = xb[64 + 9*b + k];
                        acc2_1[k] = fmaf(tb1, e, acc2_1[k]);
                        acc2_2[k] = fmaf(tb2, e, acc2_2[k]);
                    }
                }
            }

            // ================= B0-contracting paths 3, 5 ===================
            float B0[16];
            #pragma unroll
            for (int b = 0; b < 16; b++) B0[b] = xb[b];

            auto dotB0 = [&](const float* wa) -> float {
                const float4* wv = reinterpret_cast<const float4*>(wa);
                float4 q0 = wv[0], q1 = wv[1], q2 = wv[2], q3 = wv[3];
                float u0 = B0[0]*q0.x, u1 = B0[4]*q1.x, u2 = B0[8]*q2.x, u3 = B0[12]*q3.x;
                u0 = fmaf(B0[1], q0.y,u0); u0 = fmaf(B0[2], q0.z,u0); u0 = fmaf(B0[3], q0.w,u0);
                u1 = fmaf(B0[5], q1.y,u1); u1 = fmaf(B0[6], q1.z,u1); u1 = fmaf(B0[7], q1.w,u1);
                u2 = fmaf(B0[9], q2.y,u2); u2 = fmaf(B0[10],q2.z,u2); u2 = fmaf(B0[11],q2.w,u2);
                u3 = fmaf(B0[13],q3.y,u3); u3 = fmaf(B0[14],q3.z,u3); u3 = fmaf(B0[15],q3.w,u3);
                return (u0 + u1) + (u2 + u3);
            };

            // ---- path 3 (1,0)
            {
                const float* w1 = ws + ws_idx(3, 0, o1);
                const float* w2 = ws + ws_idx(3, 0, o2);
                #pragma unroll
                for (int a = 0; a < 16; a++) {
                    float s1 = dotB0(w1 + a * (16 * BPAD));
                    float s2 = dotB0(w2 + a * (16 * BPAD));
                    float e0 = xa[16 + 3*a + 0];
                    float e1 = xa[16 + 3*a + 1];
                    float e2 = xa[16 + 3*a + 2];
                    acc1_1[0] = fmaf(s1, e0, acc1_1[0]);
                    acc1_1[1] = fmaf(s1, e1, acc1_1[1]);
                    acc1_1[2] = fmaf(s1, e2, acc1_1[2]);
                    acc1_2[0] = fmaf(s2, e0, acc1_2[0]);
                    acc1_2[1] = fmaf(s2, e1, acc1_2[1]);
                    acc1_2[2] = fmaf(s2, e2, acc1_2[2]);
                }
            }

            // ---- path 5 (2,0)
            {
                const float* w1 = ws + ws_idx(5, 0, o1);
                const float* w2 = ws + ws_idx(5, 0, o2);
                #pragma unroll
                for (int a = 0; a < 16; a++) {
                    float s1 = dotB0(w1 + a * (16 * BPAD));
                    float s2 = dotB0(w2 + a * (16 * BPAD));
                    #pragma unroll
                    for (int k = 0; k < 9; k++) {
                        float e = xa[64 + 9*a + k];
                        acc2_1[k] = fmaf(s1, e, acc2_1[k]);
                        acc2_2[k] = fmaf(s2, e, acc2_2[k]);
                    }
                }
            }

            // ---- write outputs (first half of the row) for both o's
            float* orow = out + (size_t)(row0 + slot) * ROW_IN;
            orow[o1] = acc0_1;
            orow[o2] = acc0_2;
            #pragma unroll
            for (int i = 0; i < 3; i++) {
                orow[16 + 3*o1 + i] = acc1_1[i];
                orow[16 + 3*o2 + i] = acc1_2[i];
            }
            #pragma unroll
            for (int k = 0; k < 9; k++) {
                orow[64 + 9*o1 + k] = acc2_1[k];
                orow[64 + 9*o2 + k] = acc2_2[k];
            }
        }

        // ---- zero the s=1 half (cols 208..415)
        {
            float4 z = make_float4(0.f, 0.f, 0.f, 0.f);
            float4* og = reinterpret_cast<float4*>(out) + (size_t)row0 * 104;
            for (int i = tid; i < nrows * 52; i += THREADS) {
                int r = i / 52, c = i - r * 52;
                og[(size_t)r * 104 + 52 + c] = z;
            }
        }
        __syncthreads();
    }
}

extern "C" void kernel_launch(void* const* d_in, const int* in_sizes, int n_in,
                              void* d_out, int out_size)
{
    const float* x1 = (const float*)d_in[0];
    const float* x2 = (const float*)d_in[1];
    const float* w  = (const float*)d_in[2];
    float* out = (float*)d_out;
    const int N = in_sizes[0] / ROW_IN;

    const int smem_bytes = (WSM + 2 * RPT * ROW_PAD) * (int)sizeof(float); // 217856

    int smcount = 0;
    cudaDeviceGetAttribute(&smcount, cudaDevAttrMultiProcessorCount, 0);
    if (smcount <= 0) smcount = 148;
    cudaFuncSetAttribute(tp_o3_kernel, cudaFuncAttributeMaxDynamicSharedMemorySize,
                         smem_bytes);

    tp_o3_kernel<<<smcount, THREADS, smem_bytes>>>(x1, x2, w, out, N);
}

// round 7
// speedup vs baseline: 1.6007x; 1.1269x over previous
#include <cuda_runtime.h>
#include <cstdint>

// PureCartesianTensorProductO3Sparse — R7: tf32 mma.sync stage-1 + fp32 FFMA stage-2.
//
// Stage-1 (79% of MACs) = GEMMs with K=16:
//   T_p[n,(o,b)] = sum_a A0[n,a] Wp[o,a,b]          p = 0,1,2
//   S_p[n,(o,a)] = sum_b B0[n,b] Wp[o,a,b]          p = 3,5
//   V_j[n,(o,a)] = sum_b B1[n,b,j] W4[o,a,b]        j = 0,1,2
// run on the tensor pipe via mma.sync.m16n8k8.tf32 into a 32x256 smem buffer,
// one 256-col chunk per pass (8 passes). After each pass, stage-2 (exact fp32)
// contracts the buffer with per-row x operands into per-thread accumulators.

constexpr int ROW_IN  = 416;
constexpr int TILE    = 32;                // rows per CTA tile (2 m16 blocks)
constexpr int THREADS = 256;               // 8 warps
constexpr int XSTR    = 212;               // staged x row stride (floats)
constexpr int BSTR    = 260;               // buffer row stride (floats) — 8-phase banks
constexpr int WNF     = 24576;             // weight floats (fragment layout, tf32 bits)
constexpr int XNF     = TILE * XSTR;       // 6784
constexpr int BNF     = TILE * BSTR;       // 8320
// smem floats total = 24576 + 2*6784 + 8320 = 46464  (185856 B)

__device__ __forceinline__ uint32_t tf32_of(float f) {
    uint32_t u;
    asm("cvt.rna.tf32.f32 %0, %1;" : "=r"(u) : "f"(f));
    return u;
}

__device__ __forceinline__ void mma_tf32(float& d0, float& d1, float& d2, float& d3,
                                         uint32_t a0, uint32_t a1, uint32_t a2, uint32_t a3,
                                         uint32_t b0, uint32_t b1) {
    asm volatile(
        "mma.sync.aligned.m16n8k8.row.col.f32.tf32.tf32.f32 "
        "{%0,%1,%2,%3}, {%4,%5,%6,%7}, {%8,%9}, {%0,%1,%2,%3};\n"
        : "+f"(d0), "+f"(d1), "+f"(d2), "+f"(d3)
        : "r"(a0), "r"(a1), "r"(a2), "r"(a3), "r"(b0), "r"(b1));
}

__global__ __launch_bounds__(THREADS, 1)
void tp_o3_mma_kernel(const float* __restrict__ x1,
                      const float* __restrict__ x2,
                      const float* __restrict__ wgt,
                      float* __restrict__ out,
                      int N)
{
    extern __shared__ float smem[];
    float* wsF = smem;            // tf32 weight fragments
    float* x1s = smem + WNF;      // 32 x 212
    float* x2s = x1s + XNF;       // 32 x 212
    float* buf = x2s + XNF;       // 32 x 260 stage-1 chunk buffer

    const int tid = threadIdx.x;

    // ---- weight fill: gmem [p][o][a][b] -> tf32 fragment layout per slot ----
    // slots: 0,1,2 = paths 0,1,2 (k=a, col=o*16+b); 3=path3, 4=path5, 5=path4
    // (k=b, col=o*16+a).  float idx = (((slot*256+col)*8 + (k>>3)*4 + (k&3))*2 + ((k>>2)&1)
    for (int idx = tid; idx < WNF; idx += THREADS) {
        int p = idx >> 12, o = (idx >> 8) & 15, a = (idx >> 4) & 15, b = idx & 15;
        int slot, col, k;
        if (p < 3)       { slot = p; col = (o << 4) + b; k = a; }
        else if (p == 3) { slot = 3; col = (o << 4) + a; k = b; }
        else if (p == 5) { slot = 4; col = (o << 4) + a; k = b; }
        else             { slot = 5; col = (o << 4) + a; k = b; }
        int fi = ((((slot << 8) + col) << 3) + ((k >> 3) << 2) + (k & 3)) * 2 + ((k >> 2) & 1);
        wsF[fi] = __uint_as_float(tf32_of(wgt[idx]));
    }
    __syncthreads();

    const int lane = tid & 31;
    const int wid  = tid >> 5;
    const int g    = lane >> 2;      // mma group id (0..7)
    const int tg   = lane & 3;       // thread-in-group

    const int row  = tid >> 3;       // stage-2 row (0..31)
    const int os   = tid & 7;        // stage-2 o-selector
    const int o1 = os, o2 = os + 8;

    // mma phase: warp owns ntiles wid*4..wid*4+3 of the 32 (256 cols / 8)
    auto mma_pass = [&](int slot, const float* xarr, int koff, int kmul) {
        // A fragments for both 16-row blocks, both k-steps (tf32)
        uint32_t af[2][2][4];
        #pragma unroll
        for (int rb = 0; rb < 2; rb++) {
            const float* xr0 = xarr + (rb * 16 + g) * XSTR + koff;
            const float* xr1 = xr0 + 8 * XSTR;
            #pragma unroll
            for (int ks = 0; ks < 2; ks++) {
                int k0 = ks * 8 + tg, k1 = k0 + 4;
                af[rb][ks][0] = tf32_of(xr0[kmul * k0]);
                af[rb][ks][1] = tf32_of(xr1[kmul * k0]);
                af[rb][ks][2] = tf32_of(xr0[kmul * k1]);
                af[rb][ks][3] = tf32_of(xr1[kmul * k1]);
            }
        }
        #pragma unroll
        for (int j = 0; j < 4; j++) {
            int nt = wid * 4 + j;
            int col = nt * 8 + g;
            const float2* bp = reinterpret_cast<const float2*>(wsF)
                             + (((slot << 8) + col) << 3) + tg;
            float2 bk0 = bp[0];   // ks=0: (k=tg, k=tg+4)
            float2 bk1 = bp[4];   // ks=1: (k=8+tg, k=12+tg)
            uint32_t b00 = __float_as_uint(bk0.x), b01 = __float_as_uint(bk0.y);
            uint32_t b10 = __float_as_uint(bk1.x), b11 = __float_as_uint(bk1.y);
            #pragma unroll
            for (int rb = 0; rb < 2; rb++) {
                float d0 = 0.f, d1 = 0.f, d2 = 0.f, d3 = 0.f;
                mma_tf32(d0, d1, d2, d3,
                         af[rb][0][0], af[rb][0][1], af[rb][0][2], af[rb][0][3], b00, b01);
                mma_tf32(d0, d1, d2, d3,
                         af[rb][1][0], af[rb][1][1], af[rb][1][2], af[rb][1][3], b10, b11);
                int r0 = rb * 16 + g;
                int cb = nt * 8 + 2 * tg;
                *reinterpret_cast<float2*>(buf + r0 * BSTR + cb)       = make_float2(d0, d1);
                *reinterpret_cast<float2*>(buf + (r0 + 8) * BSTR + cb) = make_float2(d2, d3);
            }
        }
    };

    const int ntiles = (N + TILE - 1) / TILE;

    for (int tile = blockIdx.x; tile < ntiles; tile += (int)gridDim.x) {
        const int row0  = tile * TILE;
        const int nrows = min(TILE, N - row0);
        const bool valid = (row < nrows);

        // ---- stage used halves of rows into smem (float4) ----
        {
            const float4* g1 = reinterpret_cast<const float4*>(x1) + (size_t)row0 * 104;
            const float4* g2 = reinterpret_cast<const float4*>(x2) + (size_t)row0 * 104;
            float4* s1 = reinterpret_cast<float4*>(x1s);
            float4* s2 = reinterpret_cast<float4*>(x2s);
            for (int i = tid; i < nrows * 52; i += THREADS) {
                int r = i / 52, c = i - r * 52;
                s1[r * 53 + c] = g1[(size_t)r * 104 + c];
                s2[r * 53 + c] = g2[(size_t)r * 104 + c];
            }
        }
        __syncthreads();

        const float* xa = x1s + row * XSTR;
        const float* xb = x2s + row * XSTR;

        float acc0_1 = 0.f, acc0_2 = 0.f;
        float acc1_1[3] = {0.f,0.f,0.f}, acc1_2[3] = {0.f,0.f,0.f};
        float acc2_1[9] = {0.f,0.f,0.f,0.f,0.f,0.f,0.f,0.f,0.f};
        float acc2_2[9] = {0.f,0.f,0.f,0.f,0.f,0.f,0.f,0.f,0.f};

        float t1[16], t2[16];
        auto load_t = [&](float (&t)[16], int o) {
            const float4* p = reinterpret_cast<const float4*>(buf + row * BSTR + (o << 4));
            #pragma unroll
            for (int j = 0; j < 4; j++) {
                float4 q = p[j];
                t[4*j] = q.x; t[4*j+1] = q.y; t[4*j+2] = q.z; t[4*j+3] = q.w;
            }
        };

        // ======== pass 0: T0 (path 0) ========
        mma_pass(0, x1s, 0, 1);
        __syncthreads();
        if (valid) {
            load_t(t1, o1); load_t(t2, o2);
            float u1a=0.f,u1b=0.f,u2a=0.f,u2b=0.f;
            #pragma unroll
            for (int b = 0; b < 16; b += 2) {
                float e0 = xb[b], e1 = xb[b+1];
                u1a = fmaf(t1[b],   e0, u1a);
                u1b = fmaf(t1[b+1], e1, u1b);
                u2a = fmaf(t2[b],   e0, u2a);
                u2b = fmaf(t2[b+1], e1, u2b);
            }
            acc0_1 = u1a + u1b; acc0_2 = u2a + u2b;
        }
        __syncthreads();

        // ======== pass 1: T1 (path 1) ========
        mma_pass(1, x1s, 0, 1);
        __syncthreads();
        if (valid) {
            load_t(t1, o1); load_t(t2, o2);
            #pragma unroll
            for (int b = 0; b < 16; b++) {
                float e0 = xb[16 + 3*b + 0];
                float e1 = xb[16 + 3*b + 1];
                float e2 = xb[16 + 3*b + 2];
                acc1_1[0] = fmaf(t1[b], e0, acc1_1[0]);
                acc1_1[1] = fmaf(t1[b], e1, acc1_1[1]);
                acc1_1[2] = fmaf(t1[b], e2, acc1_1[2]);
                acc1_2[0] = fmaf(t2[b], e0, acc1_2[0]);
                acc1_2[1] = fmaf(t2[b], e1, acc1_2[1]);
                acc1_2[2] = fmaf(t2[b], e2, acc1_2[2]);
            }
        }
        __syncthreads();

        // ======== pass 2: T2 (path 2) ========
        mma_pass(2, x1s, 0, 1);
        __syncthreads();
        if (valid) {
            load_t(t1, o1); load_t(t2, o2);
            #pragma unroll
            for (int b = 0; b < 16; b++) {
                float tb1 = t1[b], tb2 = t2[b];
                #pragma unroll
                for (int k = 0; k < 9; k++) {
                    float e = xb[64 + 9*b + k];
                    acc2_1[k] = fmaf(tb1, e, acc2_1[k]);
                    acc2_2[k] = fmaf(tb2, e, acc2_2[k]);
                }
            }
        }
        __syncthreads();

        // ======== pass 3: S3 (path 3, A = B0 of x2) ========
        mma_pass(3, x2s, 0, 1);
        __syncthreads();
        if (valid) {
            load_t(t1, o1); load_t(t2, o2);
            #pragma unroll
            for (int a = 0; a < 16; a++) {
                float e0 = xa[16 + 3*a + 0];
                float e1 = xa[16 + 3*a + 1];
                float e2 = xa[16 + 3*a + 2];
                acc1_1[0] = fmaf(t1[a], e0, acc1_1[0]);
                acc1_1[1] = fmaf(t1[a], e1, acc1_1[1]);
                acc1_1[2] = fmaf(t1[a], e2, acc1_1[2]);
                acc1_2[0] = fmaf(t2[a], e0, acc1_2[0]);
                acc1_2[1] = fmaf(t2[a], e1, acc1_2[1]);
                acc1_2[2] = fmaf(t2[a], e2, acc1_2[2]);
            }
        }
        __syncthreads();

        // ======== pass 4: S5 (path 5, A = B0 of x2) ========
        mma_pass(4, x2s, 0, 1);
        __syncthreads();
        if (valid) {
            load_t(t1, o1); load_t(t2, o2);
            #pragma unroll
            for (int a = 0; a < 16; a++) {
                float s1 = t1[a], s2 = t2[a];
                #pragma unroll
                for (int k = 0; k < 9; k++) {
                    float e = xa[64 + 9*a + k];
                    acc2_1[k] = fmaf(s1, e, acc2_1[k]);
                    acc2_2[k] = fmaf(s2, e, acc2_2[k]);
                }
            }
        }
        __syncthreads();

        // ======== passes 5..7: V_j (path 4, A = B1_j of x2) ========
        #pragma unroll
        for (int jj = 0; jj < 3; jj++) {
            mma_pass(5, x2s, 16 + jj, 3);
            __syncthreads();
            if (valid) {
                load_t(t1, o1); load_t(t2, o2);
                #pragma unroll
                for (int a = 0; a < 16; a++) {
                    float v1 = t1[a], v2 = t2[a];
                    float e0 = xa[16 + 3*a + 0];
                    float e1 = xa[16 + 3*a + 1];
                    float e2 = xa[16 + 3*a + 2];
                    acc2_1[0*3 + jj] = fmaf(v1, e0, acc2_1[0*3 + jj]);
                    acc2_1[1*3 + jj] = fmaf(v1, e1, acc2_1[1*3 + jj]);
                    acc2_1[2*3 + jj] = fmaf(v1, e2, acc2_1[2*3 + jj]);
                    acc2_2[0*3 + jj] = fmaf(v2, e0, acc2_2[0*3 + jj]);
                    acc2_2[1*3 + jj] = fmaf(v2, e1, acc2_2[1*3 + jj]);
                    acc2_2[2*3 + jj] = fmaf(v2, e2, acc2_2[2*3 + jj]);
                }
            }
            __syncthreads();
        }

        // ---- write outputs (first half) ----
        if (valid) {
            float* orow = out + (size_t)(row0 + row) * ROW_IN;
            orow[o1] = acc0_1;
            orow[o2] = acc0_2;
            #pragma unroll
            for (int i = 0; i < 3; i++) {
                orow[16 + 3*o1 + i] = acc1_1[i];
                orow[16 + 3*o2 + i] = acc1_2[i];
            }
            #pragma unroll
            for (int k = 0; k < 9; k++) {
                orow[64 + 9*o1 + k] = acc2_1[k];
                orow[64 + 9*o2 + k] = acc2_2[k];
            }
        }

        // ---- zero the s=1 half (cols 208..415) ----
        {
            float4 z = make_float4(0.f, 0.f, 0.f, 0.f);
            float4* og = reinterpret_cast<float4*>(out) + (size_t)row0 * 104;
            for (int i = tid; i < nrows * 52; i += THREADS) {
                int r = i / 52, c = i - r * 52;
                og[(size_t)r * 104 + 52 + c] = z;
            }
        }
        // next tile's staging is safe: last pass's post-stage-2 sync covers smem
    }
}

extern "C" void kernel_launch(void* const* d_in, const int* in_sizes, int n_in,
                              void* d_out, int out_size)
{
    const float* x1 = (const float*)d_in[0];
    const float* x2 = (const float*)d_in[1];
    const float* w  = (const float*)d_in[2];
    float* out = (float*)d_out;
    const int N = in_sizes[0] / ROW_IN;

    const int smem_bytes = (WNF + 2 * XNF + BNF) * (int)sizeof(float);  // 185856

    int smcount = 0;
    cudaDeviceGetAttribute(&smcount, cudaDevAttrMultiProcessorCount, 0);
    if (smcount <= 0) smcount = 148;
    cudaFuncSetAttribute(tp_o3_mma_kernel, cudaFuncAttributeMaxDynamicSharedMemorySize,
                         smem_bytes);

    tp_o3_mma_kernel<<<smcount, THREADS, smem_bytes>>>(x1, x2, w, out, N);
}

// round 8
// speedup vs baseline: 1.8341x; 1.1458x over previous
#include <cuda_runtime.h>
#include <cstdint>

// PureCartesianTensorProductO3Sparse — R8: tf32 mma stage-1 + fp32 stage-2,
// double-buffered pipeline (mma pass p || stage-2 pass p-1), 16 warps.

constexpr int ROW_IN  = 416;
constexpr int TILE    = 32;                // rows per CTA tile
constexpr int THREADS = 512;               // 16 warps
constexpr int XSTR    = 212;               // staged x row stride (floats)
constexpr int BSTR    = 284;               // buffer row stride (swizzled chunks)
constexpr int WNF     = 24576;             // weight fragment floats
constexpr int XNF     = TILE * XSTR;       // 6784
constexpr int BNF     = TILE * BSTR;       // 9088
// smem = 24576 + 2*6784 + 2*9088 = 56320 floats = 225280 B

__device__ __forceinline__ uint32_t tf32_of(float f) {
    uint32_t u;
    asm("cvt.rna.tf32.f32 %0, %1;" : "=r"(u) : "f"(f));
    return u;
}

__device__ __forceinline__ void mma_tf32(float& d0, float& d1, float& d2, float& d3,
                                         uint32_t a0, uint32_t a1, uint32_t a2, uint32_t a3,
                                         uint32_t b0, uint32_t b1) {
    asm volatile(
        "mma.sync.aligned.m16n8k8.row.col.f32.tf32.tf32.f32 "
        "{%0,%1,%2,%3}, {%4,%5,%6,%7}, {%8,%9}, {%0,%1,%2,%3};\n"
        : "+f"(d0), "+f"(d1), "+f"(d2), "+f"(d3)
        : "r"(a0), "r"(a1), "r"(a2), "r"(a3), "r"(b0), "r"(b1));
}

// buffer column swizzle: col = o*16 + i  ->  phys = col + 4*(col>>5)
__device__ __forceinline__ int bswz(int col) { return col + ((col >> 5) << 2); }

__global__ __launch_bounds__(THREADS, 1)
void tp_o3_mma_kernel(const float* __restrict__ x1,
                      const float* __restrict__ x2,
                      const float* __restrict__ wgt,
                      float* __restrict__ out,
                      int N)
{
    extern __shared__ float smem[];
    float* wsF  = smem;            // tf32 weight fragments
    float* x1s  = smem + WNF;      // 32 x 212
    float* x2s  = x1s + XNF;
    float* bufA = x2s + XNF;       // 32 x 284
    float* bufB = bufA + BNF;

    const int tid = threadIdx.x;

    // ---- weight fill: gmem [p][o][a][b] -> tf32 fragment layout (as R7) ----
    for (int idx = tid; idx < WNF; idx += THREADS) {
        int p = idx >> 12, o = (idx >> 8) & 15, a = (idx >> 4) & 15, b = idx & 15;
        int slot, col, k;
        if (p < 3)       { slot = p; col = (o << 4) + b; k = a; }
        else if (p == 3) { slot = 3; col = (o << 4) + a; k = b; }
        else if (p == 5) { slot = 4; col = (o << 4) + a; k = b; }
        else             { slot = 5; col = (o << 4) + a; k = b; }
        int fi = ((((slot << 8) + col) << 3) + ((k >> 3) << 2) + (k & 3)) * 2 + ((k >> 2) & 1);
        wsF[fi] = __uint_as_float(tf32_of(wgt[idx]));
    }
    __syncthreads();

    const int lane = tid & 31;
    const int wid  = tid >> 5;
    const int g    = lane >> 2;      // mma group id
    const int tg   = lane & 3;

    const int row  = tid >> 4;       // stage-2 row (0..31)
    const int o    = tid & 15;       // stage-2 output channel

    // mma: warp = rowblock (wid>>3) x 4 n-tiles ((wid&7)*4 ..)
    auto mma_pass = [&](int slot, const float* xarr, int koff, int kmul, float* buf) {
        const int rb  = wid >> 3;
        const int nt0 = (wid & 7) << 2;
        uint32_t af[2][4];
        const float* xr0 = xarr + (rb * 16 + g) * XSTR + koff;
        const float* xr1 = xr0 + 8 * XSTR;
        #pragma unroll
        for (int ks = 0; ks < 2; ks++) {
            int k0 = ks * 8 + tg, k1 = k0 + 4;
            af[ks][0] = tf32_of(xr0[kmul * k0]);
            af[ks][1] = tf32_of(xr1[kmul * k0]);
            af[ks][2] = tf32_of(xr0[kmul * k1]);
            af[ks][3] = tf32_of(xr1[kmul * k1]);
        }
        #pragma unroll
        for (int j = 0; j < 4; j++) {
            int nt  = nt0 + j;
            int col = nt * 8 + g;
            const float2* bp = reinterpret_cast<const float2*>(wsF)
                             + (((slot << 8) + col) << 3) + tg;
            float2 bk0 = bp[0];
            float2 bk1 = bp[4];
            uint32_t b00 = __float_as_uint(bk0.x), b01 = __float_as_uint(bk0.y);
            uint32_t b10 = __float_as_uint(bk1.x), b11 = __float_as_uint(bk1.y);
            float d0 = 0.f, d1 = 0.f, d2 = 0.f, d3 = 0.f;
            mma_tf32(d0, d1, d2, d3, af[0][0], af[0][1], af[0][2], af[0][3], b00, b01);
            mma_tf32(d0, d1, d2, d3, af[1][0], af[1][1], af[1][2], af[1][3], b10, b11);
            int r0 = rb * 16 + g;
            int pc = bswz(nt * 8 + 2 * tg);
            *reinterpret_cast<float2*>(buf + r0 * BSTR + pc)       = make_float2(d0, d1);
            *reinterpret_cast<float2*>(buf + (r0 + 8) * BSTR + pc) = make_float2(d2, d3);
        }
    };

    float t[16];
    auto load_t = [&](const float* buf) {
        const float4* p = reinterpret_cast<const float4*>(
            buf + row * BSTR + (o << 4) + ((o >> 1) << 2));
        #pragma unroll
        for (int j = 0; j < 4; j++) {
            float4 q = p[j];
            t[4*j] = q.x; t[4*j+1] = q.y; t[4*j+2] = q.z; t[4*j+3] = q.w;
        }
    };

    const int ntiles = (N + TILE - 1) / TILE;

    for (int tile = blockIdx.x; tile < ntiles; tile += (int)gridDim.x) {
        const int row0  = tile * TILE;
        const int nrows = min(TILE, N - row0);
        const bool valid = (row < nrows);

        // ---- stage used halves of x rows (float4) ----
        {
            const float4* g1 = reinterpret_cast<const float4*>(x1) + (size_t)row0 * 104;
            const float4* g2 = reinterpret_cast<const float4*>(x2) + (size_t)row0 * 104;
            float4* s1 = reinterpret_cast<float4*>(x1s);
            float4* s2 = reinterpret_cast<float4*>(x2s);
            for (int i = tid; i < nrows * 52; i += THREADS) {
                int r = i / 52, c = i - r * 52;
                s1[r * 53 + c] = g1[(size_t)r * 104 + c];
                s2[r * 53 + c] = g2[(size_t)r * 104 + c];
            }
        }
        __syncthreads();

        const float* xa = x1s + row * XSTR;
        const float* xb = x2s + row * XSTR;

        float acc0 = 0.f;
        float acc1[3] = {0.f, 0.f, 0.f};
        float acc2[9] = {0.f,0.f,0.f,0.f,0.f,0.f,0.f,0.f,0.f};

        // ---- pipelined passes: mma(p) then stage2(p-1) per interval ----
        mma_pass(0, x1s, 0, 1, bufA);
        __syncthreads();

        // interval: mma T1 | stage2 path0
        mma_pass(1, x1s, 0, 1, bufB);
        if (valid) {
            load_t(bufA);
            float u0 = 0.f, u1 = 0.f;
            #pragma unroll
            for (int b = 0; b < 16; b += 2) {
                u0 = fmaf(t[b],   xb[b],   u0);
                u1 = fmaf(t[b+1], xb[b+1], u1);
            }
            acc0 = u0 + u1;
        }
        __syncthreads();

        // interval: mma T2 | stage2 path1
        mma_pass(2, x1s, 0, 1, bufA);
        if (valid) {
            load_t(bufB);
            #pragma unroll
            for (int b = 0; b < 16; b++) {
                float tb = t[b];
                acc1[0] = fmaf(tb, xb[16 + 3*b + 0], acc1[0]);
                acc1[1] = fmaf(tb, xb[16 + 3*b + 1], acc1[1]);
                acc1[2] = fmaf(tb, xb[16 + 3*b + 2], acc1[2]);
            }
        }
        __syncthreads();

        // interval: mma S3 | stage2 path2
        mma_pass(3, x2s, 0, 1, bufB);
        if (valid) {
            load_t(bufA);
            #pragma unroll
            for (int b = 0; b < 16; b++) {
                float tb = t[b];
                #pragma unroll
                for (int k = 0; k < 9; k++)
                    acc2[k] = fmaf(tb, xb[64 + 9*b + k], acc2[k]);
            }
        }
        __syncthreads();

        // interval: mma S5 | stage2 path3
        mma_pass(4, x2s, 0, 1, bufA);
        if (valid) {
            load_t(bufB);
            #pragma unroll
            for (int a = 0; a < 16; a++) {
                float s = t[a];
                acc1[0] = fmaf(s, xa[16 + 3*a + 0], acc1[0]);
                acc1[1] = fmaf(s, xa[16 + 3*a + 1], acc1[1]);
                acc1[2] = fmaf(s, xa[16 + 3*a + 2], acc1[2]);
            }
        }
        __syncthreads();

        // interval: mma V0 | stage2 path5
        mma_pass(5, x2s, 16, 3, bufB);
        if (valid) {
            load_t(bufA);
            #pragma unroll
            for (int a = 0; a < 16; a++) {
                float s = t[a];
                #pragma unroll
                for (int k = 0; k < 9; k++)
                    acc2[k] = fmaf(s, xa[64 + 9*a + k], acc2[k]);
            }
        }
        __syncthreads();

        // interval: mma V1 | stage2 V0
        mma_pass(5, x2s, 17, 3, bufA);
        if (valid) {
            load_t(bufB);
            #pragma unroll
            for (int a = 0; a < 16; a++) {
                float v = t[a];
                acc2[0] = fmaf(v, xa[16 + 3*a + 0], acc2[0]);
                acc2[3] = fmaf(v, xa[16 + 3*a + 1], acc2[3]);
                acc2[6] = fmaf(v, xa[16 + 3*a + 2], acc2[6]);
            }
        }
        __syncthreads();

        // interval: mma V2 | stage2 V1
        mma_pass(5, x2s, 18, 3, bufB);
        if (valid) {
            load_t(bufA);
            #pragma unroll
            for (int a = 0; a < 16; a++) {
                float v = t[a];
                acc2[1] = fmaf(v, xa[16 + 3*a + 0], acc2[1]);
                acc2[4] = fmaf(v, xa[16 + 3*a + 1], acc2[4]);
                acc2[7] = fmaf(v, xa[16 + 3*a + 2], acc2[7]);
            }
        }
        __syncthreads();

        // final: stage2 V2
        if (valid) {
            load_t(bufB);
            #pragma unroll
            for (int a = 0; a < 16; a++) {
                float v = t[a];
                acc2[2] = fmaf(v, xa[16 + 3*a + 0], acc2[2]);
                acc2[5] = fmaf(v, xa[16 + 3*a + 1], acc2[5]);
                acc2[8] = fmaf(v, xa[16 + 3*a + 2], acc2[8]);
            }

            // ---- write outputs (first half) ----
            float* orow = out + (size_t)(row0 + row) * ROW_IN;
            orow[o] = acc0;
            #pragma unroll
            for (int i = 0; i < 3; i++) orow[16 + 3*o + i] = acc1[i];
            #pragma unroll
            for (int k = 0; k < 9; k++) orow[64 + 9*o + k] = acc2[k];
        }

        // ---- zero the s=1 half (cols 208..415) ----
        {
            float4 z = make_float4(0.f, 0.f, 0.f, 0.f);
            float4* og = reinterpret_cast<float4*>(out) + (size_t)row0 * 104;
            for (int i = tid; i < nrows * 52; i += THREADS) {
                int r = i / 52, c = i - r * 52;
                og[(size_t)r * 104 + 52 + c] = z;
            }
        }
        __syncthreads();   // protect x staging + buffers for next tile
    }
}

extern "C" void kernel_launch(void* const* d_in, const int* in_sizes, int n_in,
                              void* d_out, int out_size)
{
    const float* x1 = (const float*)d_in[0];
    const float* x2 = (const float*)d_in[1];
    const float* w  = (const float*)d_in[2];
    float* out = (float*)d_out;
    const int N = in_sizes[0] / ROW_IN;

    const int smem_bytes = (WNF + 2 * XNF + 2 * BNF) * (int)sizeof(float);  // 225280

    int smcount = 0;
    cudaDeviceGetAttribute(&smcount, cudaDevAttrMultiProcessorCount, 0);
    if (smcount <= 0) smcount = 148;
    cudaFuncSetAttribute(tp_o3_mma_kernel, cudaFuncAttributeMaxDynamicSharedMemorySize,
                         smem_bytes);

    tp_o3_mma_kernel<<<smcount, THREADS, smem_bytes>>>(x1, x2, w, out, N);
}

// round 9
// speedup vs baseline: 2.0580x; 1.1221x over previous
#include <cuda_runtime.h>
#include <cstdint>

// PureCartesianTensorProductO3Sparse — R9: warp-specialized producer/consumer.
// Warps 0-7 (producers) run tf32 mma stage-1 passes into ping-pong smem
// buffers; warps 8-15 (consumers) run exact-fp32 stage-2. Named barriers
// (ids 1-4, count 512) implement the full/empty handshake per buffer slot.

constexpr int ROW_IN  = 416;
constexpr int TILE    = 32;
constexpr int THREADS = 512;               // 8 producer + 8 consumer warps
constexpr int XSTR    = 212;
constexpr int BSTR    = 284;
constexpr int WNF     = 24576;
constexpr int XNF     = TILE * XSTR;       // 6784
constexpr int BNF     = TILE * BSTR;       // 9088
// smem = 24576 + 2*6784 + 2*9088 = 56320 floats = 225280 B

#define BAR_ARRIVE(id) asm volatile("bar.arrive %0, %1;" :: "r"(id), "r"(THREADS) : "memory")
#define BAR_SYNC(id)   asm volatile("bar.sync %0, %1;"   :: "r"(id), "r"(THREADS) : "memory")
// barrier ids: full[slot] = 1 + slot, empty[slot] = 3 + slot

__device__ __forceinline__ uint32_t tf32_of(float f) {
    uint32_t u;
    asm("cvt.rna.tf32.f32 %0, %1;" : "=r"(u) : "f"(f));
    return u;
}

__device__ __forceinline__ void mma_tf32(float& d0, float& d1, float& d2, float& d3,
                                         uint32_t a0, uint32_t a1, uint32_t a2, uint32_t a3,
                                         uint32_t b0, uint32_t b1) {
    asm volatile(
        "mma.sync.aligned.m16n8k8.row.col.f32.tf32.tf32.f32 "
        "{%0,%1,%2,%3}, {%4,%5,%6,%7}, {%8,%9}, {%0,%1,%2,%3};\n"
        : "+f"(d0), "+f"(d1), "+f"(d2), "+f"(d3)
        : "r"(a0), "r"(a1), "r"(a2), "r"(a3), "r"(b0), "r"(b1));
}

__device__ __forceinline__ int bswz(int col) { return col + ((col >> 5) << 2); }

__global__ __launch_bounds__(THREADS, 1)
void tp_o3_mma_kernel(const float* __restrict__ x1,
                      const float* __restrict__ x2,
                      const float* __restrict__ wgt,
                      float* __restrict__ out,
                      int N)
{
    extern __shared__ float smem[];
    float* wsF  = smem;
    float* x1s  = smem + WNF;
    float* x2s  = x1s + XNF;
    float* bufs[2] = { x2s + XNF, x2s + XNF + BNF };

    const int tid = threadIdx.x;

    // ---- weight fill: gmem [p][o][a][b] -> tf32 fragment layout ----
    for (int idx = tid; idx < WNF; idx += THREADS) {
        int p = idx >> 12, o = (idx >> 8) & 15, a = (idx >> 4) & 15, b = idx & 15;
        int slot, col, k;
        if (p < 3)       { slot = p; col = (o << 4) + b; k = a; }
        else if (p == 3) { slot = 3; col = (o << 4) + a; k = b; }
        else if (p == 5) { slot = 4; col = (o << 4) + a; k = b; }
        else             { slot = 5; col = (o << 4) + a; k = b; }
        int fi = ((((slot << 8) + col) << 3) + ((k >> 3) << 2) + (k & 3)) * 2 + ((k >> 2) & 1);
        wsF[fi] = __uint_as_float(tf32_of(wgt[idx]));
    }
    __syncthreads();

    const int lane = tid & 31;
    const int wid  = tid >> 5;
    const bool producer = (wid < 8);

    // consumers pre-arrive both empty slots so producer waits are uniform
    if (!producer) { BAR_ARRIVE(3); BAR_ARRIVE(4); }

    const int ntiles = (N + TILE - 1) / TILE;

    if (producer) {
        // ---------------- PRODUCER: mma stage-1 ----------------
        const int g   = lane >> 2;
        const int tg  = lane & 3;
        const int rb  = wid >> 2;           // rowblock 0/1
        const int nt0 = (wid & 3) << 3;     // 8 n-tiles per warp

        for (int tile = blockIdx.x; tile < ntiles; tile += (int)gridDim.x) {
            const int row0  = tile * TILE;
            const int nrows = min(TILE, N - row0);

            __syncthreads();   // consumers done with previous x
            // stage x rows (producer half of the work: i stride THREADS w/ offset)
            {
                const float4* g1 = reinterpret_cast<const float4*>(x1) + (size_t)row0 * 104;
                const float4* g2 = reinterpret_cast<const float4*>(x2) + (size_t)row0 * 104;
                float4* s1 = reinterpret_cast<float4*>(x1s);
                float4* s2 = reinterpret_cast<float4*>(x2s);
                for (int i = tid; i < nrows * 52; i += THREADS) {
                    int r = i / 52, c = i - r * 52;
                    s1[r * 53 + c] = g1[(size_t)r * 104 + c];
                    s2[r * 53 + c] = g2[(size_t)r * 104 + c];
                }
            }
            __syncthreads();   // staging complete

            #pragma unroll
            for (int p = 0; p < 8; p++) {
                const int s = p & 1;
                // pass -> (slot, src, koff, kmul)
                const int  slot = (p < 3) ? p : (p == 3 ? 3 : (p == 4 ? 4 : 5));
                const float* xarr = (p < 3) ? x1s : x2s;
                const int  koff = (p < 5) ? 0 : (16 + (p - 5));
                const int  kmul = (p < 5) ? 1 : 3;

                BAR_SYNC(3 + s);            // wait slot empty
                float* buf = bufs[s];

                uint32_t af[2][4];
                const float* xr0 = xarr + (rb * 16 + g) * XSTR + koff;
                const float* xr1 = xr0 + 8 * XSTR;
                #pragma unroll
                for (int ks = 0; ks < 2; ks++) {
                    int k0 = ks * 8 + tg, k1 = k0 + 4;
                    af[ks][0] = tf32_of(xr0[kmul * k0]);
                    af[ks][1] = tf32_of(xr1[kmul * k0]);
                    af[ks][2] = tf32_of(xr0[kmul * k1]);
                    af[ks][3] = tf32_of(xr1[kmul * k1]);
                }
                #pragma unroll
                for (int j = 0; j < 8; j++) {
                    int nt  = nt0 + j;
                    int col = nt * 8 + g;
                    const float2* bp = reinterpret_cast<const float2*>(wsF)
                                     + (((slot << 8) + col) << 3) + tg;
                    float2 bk0 = bp[0];
                    float2 bk1 = bp[4];
                    uint32_t b00 = __float_as_uint(bk0.x), b01 = __float_as_uint(bk0.y);
                    uint32_t b10 = __float_as_uint(bk1.x), b11 = __float_as_uint(bk1.y);
                    float d0 = 0.f, d1 = 0.f, d2 = 0.f, d3 = 0.f;
                    mma_tf32(d0, d1, d2, d3, af[0][0], af[0][1], af[0][2], af[0][3], b00, b01);
                    mma_tf32(d0, d1, d2, d3, af[1][0], af[1][1], af[1][2], af[1][3], b10, b11);
                    int r0 = rb * 16 + g;
                    int pc = bswz(nt * 8 + 2 * tg);
                    *reinterpret_cast<float2*>(buf + r0 * BSTR + pc)       = make_float2(d0, d1);
                    *reinterpret_cast<float2*>(buf + (r0 + 8) * BSTR + pc) = make_float2(d2, d3);
                }
                BAR_ARRIVE(1 + s);          // slot full
            }

            // zero the s=1 output half while consumers finish
            {
                float4 z = make_float4(0.f, 0.f, 0.f, 0.f);
                float4* og = reinterpret_cast<float4*>(out) + (size_t)row0 * 104;
                for (int i = tid; i < nrows * 52; i += 256) {
                    int r = i / 52, c = i - r * 52;
                    og[(size_t)r * 104 + 52 + c] = z;
                }
            }
        }
    } else {
        // ---------------- CONSUMER: fp32 stage-2 ----------------
        const int ctid = tid - 256;
        const int row  = ctid >> 3;         // 0..31
        const int os   = ctid & 7;
        const int o1 = os, o2 = os + 8;
        const int toff1 = bswz(o1 << 4);
        const int toff2 = bswz(o2 << 4);

        float t1[16], t2[16];

        for (int tile = blockIdx.x; tile < ntiles; tile += (int)gridDim.x) {
            const int row0  = tile * TILE;
            const int nrows = min(TILE, N - row0);
            const bool valid = (row < nrows);

            __syncthreads();
            {
                const float4* g1 = reinterpret_cast<const float4*>(x1) + (size_t)row0 * 104;
                const float4* g2 = reinterpret_cast<const float4*>(x2) + (size_t)row0 * 104;
                float4* s1 = reinterpret_cast<float4*>(x1s);
                float4* s2 = reinterpret_cast<float4*>(x2s);
                for (int i = tid; i < nrows * 52; i += THREADS) {
                    int r = i / 52, c = i - r * 52;
                    s1[r * 53 + c] = g1[(size_t)r * 104 + c];
                    s2[r * 53 + c] = g2[(size_t)r * 104 + c];
                }
            }
            __syncthreads();

            const float* xa = x1s + row * XSTR;
            const float* xb = x2s + row * XSTR;

            float acc0_1 = 0.f, acc0_2 = 0.f;
            float acc1_1[3] = {0.f,0.f,0.f}, acc1_2[3] = {0.f,0.f,0.f};
            float acc2_1[9] = {0.f,0.f,0.f,0.f,0.f,0.f,0.f,0.f,0.f};
            float acc2_2[9] = {0.f,0.f,0.f,0.f,0.f,0.f,0.f,0.f,0.f};

            auto load_tt = [&](const float* buf) {
                const float4* p1 = reinterpret_cast<const float4*>(buf + row * BSTR + toff1);
                const float4* p2 = reinterpret_cast<const float4*>(buf + row * BSTR + toff2);
                #pragma unroll
                for (int j = 0; j < 4; j++) {
                    float4 q = p1[j];
                    t1[4*j] = q.x; t1[4*j+1] = q.y; t1[4*j+2] = q.z; t1[4*j+3] = q.w;
                    q = p2[j];
                    t2[4*j] = q.x; t2[4*j+1] = q.y; t2[4*j+2] = q.z; t2[4*j+3] = q.w;
                }
            };

            #pragma unroll
            for (int p = 0; p < 8; p++) {
                const int s = p & 1;
                BAR_SYNC(1 + s);            // wait slot full
                if (valid) {
                    load_tt(bufs[s]);
                    if (p == 0) {
                        float u1a=0.f,u1b=0.f,u2a=0.f,u2b=0.f;
                        #pragma unroll
                        for (int b = 0; b < 16; b += 2) {
                            float e0 = xb[b], e1 = xb[b+1];
                            u1a = fmaf(t1[b],   e0, u1a);
                            u1b = fmaf(t1[b+1], e1, u1b);
                            u2a = fmaf(t2[b],   e0, u2a);
                            u2b = fmaf(t2[b+1], e1, u2b);
                        }
                        acc0_1 = u1a + u1b; acc0_2 = u2a + u2b;
                    } else if (p == 1) {
                        #pragma unroll
                        for (int b = 0; b < 16; b++) {
                            float e0 = xb[16 + 3*b + 0];
                            float e1 = xb[16 + 3*b + 1];
                            float e2 = xb[16 + 3*b + 2];
                            acc1_1[0] = fmaf(t1[b], e0, acc1_1[0]);
                            acc1_1[1] = fmaf(t1[b], e1, acc1_1[1]);
                            acc1_1[2] = fmaf(t1[b], e2, acc1_1[2]);
                            acc1_2[0] = fmaf(t2[b], e0, acc1_2[0]);
                            acc1_2[1] = fmaf(t2[b], e1, acc1_2[1]);
                            acc1_2[2] = fmaf(t2[b], e2, acc1_2[2]);
                        }
                    } else if (p == 2) {
                        #pragma unroll
                        for (int b = 0; b < 16; b++) {
                            float tb1 = t1[b], tb2 = t2[b];
                            #pragma unroll
                            for (int k = 0; k < 9; k++) {
                                float e = xb[64 + 9*b + k];
                                acc2_1[k] = fmaf(tb1, e, acc2_1[k]);
                                acc2_2[k] = fmaf(tb2, e, acc2_2[k]);
                            }
                        }
                    } else if (p == 3) {
                        #pragma unroll
                        for (int a = 0; a < 16; a++) {
                            float e0 = xa[16 + 3*a + 0];
                            float e1 = xa[16 + 3*a + 1];
                            float e2 = xa[16 + 3*a + 2];
                            acc1_1[0] = fmaf(t1[a], e0, acc1_1[0]);
                            acc1_1[1] = fmaf(t1[a], e1, acc1_1[1]);
                            acc1_1[2] = fmaf(t1[a], e2, acc1_1[2]);
                            acc1_2[0] = fmaf(t2[a], e0, acc1_2[0]);
                            acc1_2[1] = fmaf(t2[a], e1, acc1_2[1]);
                            acc1_2[2] = fmaf(t2[a], e2, acc1_2[2]);
                        }
                    } else if (p == 4) {
                        #pragma unroll
                        for (int a = 0; a < 16; a++) {
                            float s1v = t1[a], s2v = t2[a];
                            #pragma unroll
                            for (int k = 0; k < 9; k++) {
                                float e = xa[64 + 9*a + k];
                                acc2_1[k] = fmaf(s1v, e, acc2_1[k]);
                                acc2_2[k] = fmaf(s2v, e, acc2_2[k]);
                            }
                        }
                    } else {
                        const int jj = p - 5;
                        #pragma unroll
                        for (int a = 0; a < 16; a++) {
                            float v1 = t1[a], v2 = t2[a];
                            float e0 = xa[16 + 3*a + 0];
                            float e1 = xa[16 + 3*a + 1];
                            float e2 = xa[16 + 3*a + 2];
                            acc2_1[0 + jj] = fmaf(v1, e0, acc2_1[0 + jj]);
                            acc2_1[3 + jj] = fmaf(v1, e1, acc2_1[3 + jj]);
                            acc2_1[6 + jj] = fmaf(v1, e2, acc2_1[6 + jj]);
                            acc2_2[0 + jj] = fmaf(v2, e0, acc2_2[0 + jj]);
                            acc2_2[3 + jj] = fmaf(v2, e1, acc2_2[3 + jj]);
                            acc2_2[6 + jj] = fmaf(v2, e2, acc2_2[6 + jj]);
                        }
                    }
                }
                BAR_ARRIVE(3 + s);          // slot empty
            }

            // ---- write outputs (first half) for both o's ----
            if (valid) {
                float* orow = out + (size_t)(row0 + row) * ROW_IN;
                orow[o1] = acc0_1;
                orow[o2] = acc0_2;
                #pragma unroll
                for (int i = 0; i < 3; i++) {
                    orow[16 + 3*o1 + i] = acc1_1[i];
                    orow[16 + 3*o2 + i] = acc1_2[i];
                }
                #pragma unroll
                for (int k = 0; k < 9; k++) {
                    orow[64 + 9*o1 + k] = acc2_1[k];
                    orow[64 + 9*o2 + k] = acc2_2[k];
                }
            }
        }
    }
}

extern "C" void kernel_launch(void* const* d_in, const int* in_sizes, int n_in,
                              void* d_out, int out_size)
{
    const float* x1 = (const float*)d_in[0];
    const float* x2 = (const float*)d_in[1];
    const float* w  = (const float*)d_in[2];
    float* out = (float*)d_out;
    const int N = in_sizes[0] / ROW_IN;

    const int smem_bytes = (WNF + 2 * XNF + 2 * BNF) * (int)sizeof(float);  // 225280

    int smcount = 0;
    cudaDeviceGetAttribute(&smcount, cudaDevAttrMultiProcessorCount, 0);
    if (smcount <= 0) smcount = 148;
    cudaFuncSetAttribute(tp_o3_mma_kernel, cudaFuncAttributeMaxDynamicSharedMemorySize,
                         smem_bytes);

    tp_o3_mma_kernel<<<smcount, THREADS, smem_bytes>>>(x1, x2, w, out, N);
}